// round 16
// baseline (speedup 1.0000x reference)
#include <cuda_runtime.h>

#define BB 2
#define NN 40000
#define EE 400000
#define RR 64
#define DD 64
#define LLAYERS 6
#define MASKW 1250   // (NN+31)/32
#define SCANB 157    // (NN+255)/256
#define INITB 5000   // BB*NN*DD/4/256
#define RELB 192     // LLAYERS*BB*RR/4
#define HISTB 1563   // (EE+255)/256

#define FMA2(acc, a, b) \
    asm("fma.rn.f32x2 %0, %1, %2, %0;" : "+l"(acc) : "l"(a), "l"(b))
#define ADD2(dst, a, b) \
    asm("add.rn.f32x2 %0, %1, %2;" : "=l"(dst) : "l"(a), "l"(b))
#define PACK2(dst, lo, hi) \
    asm("mov.b64 %0, {%1,%2};" : "=l"(dst) : "r"(__float_as_uint(lo)), "r"(__float_as_uint(hi)))
#define DUP2(dst, v) \
    asm("mov.b64 %0, {%1,%1};" : "=l"(dst) : "r"(__float_as_uint(v)))
#define UNPACK2(lo, hi, src)                          \
    do {                                              \
        unsigned _ulo, _uhi;                          \
        asm("mov.b64 {%0,%1}, %2;"                    \
            : "=r"(_ulo), "=r"(_uhi) : "l"(src));     \
        lo = __uint_as_float(_ulo);                   \
        hi = __uint_as_float(_uhi);                   \
    } while (0)

// Scratch (allocation-free rule: __device__ globals)
__device__ __align__(16) float g_x[BB * NN * DD];
__device__ __align__(16) float g_agg[BB * NN * DD];  // gather OVERWRITES listed rows every layer
__device__ __align__(16) float g_rel[LLAYERS * BB * RR * DD];
__device__ __align__(16) float g_query[BB * DD];
__device__ __align__(16) float g_qpart[BB * 2 * DD];
__device__ unsigned g_mask[BB * MASKW];  // bit set <=> node is in g_list
__device__ int g_list[BB * NN];          // persistent, monotone across layers
__device__ int g_count[BB];
__device__ int g_dense;
// CSR by dst (shared by both batches — same graph); {src,ty} materialized
__device__ int g_cnt[NN];  // zero at launch entry/exit (BSS + scan1 restore)
__device__ int g_fill[NN];
__device__ int g_csr_ptr[NN + 1];
__device__ __align__(16) int2 g_csr_st[EE];
__device__ int g_bsum[SCANB + 3];

// ---------------------------------------------------------------------------
// prep: masks, query, dense flag, list seed {h}, qpart
// ---------------------------------------------------------------------------
__global__ void prep_kernel(const float* __restrict__ rel_reps,
                            const int* __restrict__ r_index,
                            const int* __restrict__ h_index,
                            const float* __restrict__ mlp_w,
                            const float* __restrict__ mlp_b,
                            const float* __restrict__ lin_b,
                            const float* __restrict__ ln_g,
                            const float* __restrict__ ln_b) {
    __shared__ float q_s[BB * DD];
    int t = threadIdx.x;  // 256
    for (int i = t; i < BB * MASKW; i += 256) g_mask[i] = 0u;
    if (t < BB * DD) {
        int b = t / DD, d = t % DD;
        float v = rel_reps[(b * RR + r_index[b]) * DD + d];
        g_query[t] = v;
        q_s[t] = v;
    }
    if (t == 0) {
        int dense = 0;
        for (int l = 0; l < LLAYERS; l++) {
            const float* lb = lin_b + l * DD;
            float mu = 0.f;
            for (int d = 0; d < DD; d++) mu += lb[d];
            mu *= (1.f / DD);
            float var = 0.f;
            for (int d = 0; d < DD; d++) {
                float dv = lb[d] - mu;
                var += dv * dv;
            }
            var *= (1.f / DD);
            float inv = rsqrtf(var + 1e-5f);
            for (int d = 0; d < DD; d++) {
                float o = (lb[d] - mu) * inv * ln_g[l * DD + d] + ln_b[l * DD + d];
                if (o > 0.f) dense = 1;
            }
        }
        g_dense = dense;
    }
    __syncthreads();
    if (t < BB) {
        int h = h_index[t];
        g_mask[t * MASKW + (h >> 5)] = 1u << (h & 31);
        g_count[t] = g_dense ? NN : 1;
        g_list[t * NN] = h;
    }
    int b = t / 128, e = t % 128;
    float acc = mlp_b[e];
#pragma unroll
    for (int k = 0; k < DD; k++)
        acc = fmaf(q_s[b * DD + k], mlp_w[(DD + k) * 128 + e], acc);
    g_qpart[b * 128 + e] = acc;
}

// ---------------------------------------------------------------------------
// setup: init_x (+ dense-fallback list/mask) ∪ relproj_all ∪ csr_hist
// ---------------------------------------------------------------------------
__global__ void setup_kernel(const int* __restrict__ h_index,
                             const float* __restrict__ rel_reps,
                             const float* __restrict__ pw1,
                             const float* __restrict__ pb1,
                             const float* __restrict__ pw2,
                             const float* __restrict__ pb2,
                             const int* __restrict__ edge_index) {
    int bid = blockIdx.x;
    int t = threadIdx.x;  // 256
    if (bid < INITB) {
        int gid = bid * 256 + t;
        const int per_b = NN * DD / 4;
        if (gid >= BB * per_b) return;
        if (g_dense) {
            if (gid < BB * NN) g_list[gid] = gid % NN;
            if (gid < BB * MASKW) g_mask[gid] = 0xffffffffu;
        }
        int b = gid / per_b;
        int r = gid - b * per_b;
        int n = r >> 4;
        int d4 = r & 15;
        float4 v = make_float4(0.f, 0.f, 0.f, 0.f);
        if (n == __ldg(&h_index[b]))
            v = *(const float4*)&g_query[b * DD + d4 * 4];
        ((float4*)g_x)[gid] = v;
    } else if (bid < INITB + RELB) {
        __shared__ float in_s[4][DD];
        __shared__ float hid_s[4][DD];
        int pair = (bid - INITB) * 4 + (t >> 6);
        int g = t >> 6;
        int e = t & 63;
        int l = pair / (BB * RR);
        int br = pair - l * (BB * RR);
        in_s[g][e] = rel_reps[br * DD + e];
        __syncthreads();
        const float* W1 = pw1 + l * DD * DD;
        float acc = pb1[l * DD + e];
#pragma unroll 16
        for (int k = 0; k < DD; k++) acc = fmaf(in_s[g][k], W1[k * DD + e], acc);
        hid_s[g][e] = fmaxf(acc, 0.f);
        __syncthreads();
        const float* W2 = pw2 + l * DD * DD;
        float acc2 = pb2[l * DD + e];
#pragma unroll 16
        for (int k = 0; k < DD; k++)
            acc2 = fmaf(hid_s[g][k], W2[k * DD + e], acc2);
        g_rel[pair * DD + e] = acc2;
    } else {
        int e = (bid - INITB - RELB) * 256 + t;
        if (e < EE) atomicAdd(&g_cnt[__ldg(&edge_index[EE + e])], 1);
    }
}

// ---------------------------------------------------------------------------
// CSR scan/scatter
// ---------------------------------------------------------------------------
__global__ void csr_scan1() {
    __shared__ int sh[256];
    int t = threadIdx.x;
    int i = blockIdx.x * 256 + t;
    int v = 0;
    if (i < NN) {
        v = g_cnt[i];
        g_cnt[i] = 0;
    }
    sh[t] = v;
    __syncthreads();
#pragma unroll
    for (int off = 1; off < 256; off <<= 1) {
        int u = (t >= off) ? sh[t - off] : 0;
        __syncthreads();
        sh[t] += u;
        __syncthreads();
    }
    if (t == 255) g_bsum[blockIdx.x] = sh[255];
    if (i < NN) g_csr_ptr[i] = sh[t] - v;
}
__global__ void csr_scan3() {
    __shared__ int sh[256];
    int t = threadIdx.x;
    int v = (t < SCANB) ? g_bsum[t] : 0;
    sh[t] = v;
    __syncthreads();
#pragma unroll
    for (int off = 1; off < 256; off <<= 1) {
        int u = (t >= off) ? sh[t - off] : 0;
        __syncthreads();
        sh[t] += u;
        __syncthreads();
    }
    __shared__ int s_off;
    if (t == 0) s_off = (blockIdx.x == 0) ? 0 : sh[blockIdx.x - 1];
    __syncthreads();
    int i = blockIdx.x * 256 + t;
    if (i < NN) {
        int p = g_csr_ptr[i] + s_off;
        g_csr_ptr[i] = p;
        g_fill[i] = p;
    }
    if (i == 0) g_csr_ptr[NN] = EE;
}
__global__ void csr_scatter(const int* __restrict__ edge_index,
                            const int* __restrict__ edge_type) {
    int e = blockIdx.x * 256 + threadIdx.x;
    if (e >= EE) return;
    int src = __ldg(&edge_index[e]);
    int dst = __ldg(&edge_index[EE + e]);
    int ty = __ldg(&edge_type[e]);
    int pos = atomicAdd(&g_fill[dst], 1);
    g_csr_st[pos] = make_int2(src, ty);
}

// ---------------------------------------------------------------------------
// gather message: warp per dst, BOTH batches per pass.
// Dense fast path: half-warp per edge, 16 lanes x 4 dims, LDG.128 loads —
// warp retires 2 edges/iter with ~40% fewer instructions. Partial sums of
// even/odd edges combined via shfl_xor(16) + packed add.
// Sparse path: mask probe + ballot + shfl extraction.
// ---------------------------------------------------------------------------
__global__ void __launch_bounds__(256)
gather_kernel(const int* __restrict__ h_index, int l) {
    const unsigned FULL = 0xffffffffu;
    __shared__ int s_list0[8], s_list1[8];
    __shared__ int s_n0, s_n1, s_b0, s_b1;
    if (threadIdx.x == 0) { s_n0 = 0; s_n1 = 0; }
    int dst = blockIdx.x * 8 + (threadIdx.x >> 5);  // NN % 8 == 0
    int lane = threadIdx.x & 31;
    const unsigned* m0 = g_mask;
    const unsigned* m1 = g_mask + MASKW;
    const float* rel0 = g_rel + (l * BB + 0) * RR * DD;
    const float* rel1 = g_rel + (l * BB + 1) * RR * DD;
    bool dense_now = (g_count[0] == NN) && (g_count[1] == NN);
    int beg = __ldg(&g_csr_ptr[dst]);
    int end = __ldg(&g_csr_ptr[dst + 1]);
    int h0 = __ldg(&h_index[0]);
    int h1 = __ldg(&h_index[1]);
    __syncthreads();

    if (dense_now) {
        // half-warp per edge: hw = lane>>4 takes edges beg+2i+hw
        int hl = lane & 15;  // dims 4*hl .. 4*hl+3
        int hw = lane >> 4;
        unsigned long long a0x = 0ull, a0y = 0ull;  // batch0 dims {4hl,4hl+1},{4hl+2,4hl+3}
        unsigned long long a1x = 0ull, a1y = 0ull;  // batch1
        for (int i = beg + hw; i < end; i += 2) {
            int2 st = __ldg(&g_csr_st[i]);  // uniform within half-warp
            const ulonglong2 xv0 =
                *(const ulonglong2*)&g_x[st.x * DD + hl * 4];
            const ulonglong2 rv0 =
                *(const ulonglong2*)&rel0[st.y * DD + hl * 4];
            const ulonglong2 xv1 =
                *(const ulonglong2*)&g_x[(NN + st.x) * DD + hl * 4];
            const ulonglong2 rv1 =
                *(const ulonglong2*)&rel1[st.y * DD + hl * 4];
            FMA2(a0x, xv0.x, rv0.x);
            FMA2(a0y, xv0.y, rv0.y);
            FMA2(a1x, xv1.x, rv1.x);
            FMA2(a1y, xv1.y, rv1.y);
        }
        // combine even/odd-edge partials across half-warps
        unsigned long long t0x = __shfl_xor_sync(FULL, a0x, 16);
        unsigned long long t0y = __shfl_xor_sync(FULL, a0y, 16);
        unsigned long long t1x = __shfl_xor_sync(FULL, a1x, 16);
        unsigned long long t1y = __shfl_xor_sync(FULL, a1y, 16);
        ADD2(a0x, a0x, t0x);
        ADD2(a0y, a0y, t0y);
        ADD2(a1x, a1x, t1x);
        ADD2(a1y, a1y, t1y);
        if (hw == 0) {
            float o[4];
            UNPACK2(o[0], o[1], a0x);
            UNPACK2(o[2], o[3], a0y);
            if (dst == h0) {
                float4 q = *(const float4*)&g_query[hl * 4];
                o[0] += q.x; o[1] += q.y; o[2] += q.z; o[3] += q.w;
            }
            bool any0 = (beg < end) || (dst == h0);
            if (any0)
                *(float4*)&g_agg[dst * DD + hl * 4] =
                    make_float4(o[0], o[1], o[2], o[3]);
            float p[4];
            UNPACK2(p[0], p[1], a1x);
            UNPACK2(p[2], p[3], a1y);
            if (dst == h1) {
                float4 q = *(const float4*)&g_query[DD + hl * 4];
                p[0] += q.x; p[1] += q.y; p[2] += q.z; p[3] += q.w;
            }
            bool any1 = (beg < end) || (dst == h1);
            if (any1)
                *(float4*)&g_agg[(NN + dst) * DD + hl * 4] =
                    make_float4(p[0], p[1], p[2], p[3]);
        }
        return;  // masks full, no appends possible
    }

    // ---- sparse path ----
    unsigned long long acc0 = 0ull, acc1 = 0ull;
    bool any0 = false, any1 = false;
    for (int base = beg; base < end; base += 32) {
        int i = base + lane;
        int src = 0, ty = 0;
        bool a0 = false, a1 = false;
        if (i < end) {
            int2 st = __ldg(&g_csr_st[i]);  // coalesced 8B load
            src = st.x;
            ty = st.y;
            a0 = (m0[src >> 5] >> (src & 31)) & 1u;
            a1 = (m1[src >> 5] >> (src & 31)) & 1u;
        }
        unsigned ball0 = __ballot_sync(FULL, a0);
        unsigned ball1 = __ballot_sync(FULL, a1);
        any0 |= (ball0 != 0);
        any1 |= (ball1 != 0);
        unsigned ball = ball0 | ball1;
        while (ball) {
            int lx = __ffs(ball) - 1;
            ball &= ball - 1;
            int s = __shfl_sync(FULL, src, lx);
            int tt = __shfl_sync(FULL, ty, lx);
            if ((ball0 >> lx) & 1u) {
                unsigned long long xv =
                    *(const unsigned long long*)&g_x[s * DD + lane * 2];
                unsigned long long rv =
                    *(const unsigned long long*)&rel0[tt * DD + lane * 2];
                FMA2(acc0, xv, rv);
            }
            if ((ball1 >> lx) & 1u) {
                unsigned long long xv = *(
                    const unsigned long long*)&g_x[(NN + s) * DD + lane * 2];
                unsigned long long rv =
                    *(const unsigned long long*)&rel1[tt * DD + lane * 2];
                FMA2(acc1, xv, rv);
            }
        }
    }
    float a0x, a0y, a1x, a1y;
    UNPACK2(a0x, a0y, acc0);
    UNPACK2(a1x, a1y, acc1);
    if (dst == h0) {
        float2 q = *(const float2*)&g_query[lane * 2];
        a0x += q.x; a0y += q.y;
        any0 = true;
    }
    if (dst == h1) {
        float2 q = *(const float2*)&g_query[DD + lane * 2];
        a1x += q.x; a1y += q.y;
        any1 = true;
    }
    if (any0)
        *(float2*)&g_agg[dst * DD + lane * 2] = make_float2(a0x, a0y);
    if (any1)
        *(float2*)&g_agg[(NN + dst) * DD + lane * 2] = make_float2(a1x, a1y);
    if (any0 && lane == 0) {
        unsigned bit = 1u << (dst & 31);
        if (!(m0[dst >> 5] & bit)) {
            unsigned old = atomicOr(&g_mask[dst >> 5], bit);
            if (!(old & bit)) s_list0[atomicAdd(&s_n0, 1)] = dst;
        }
    }
    if (any1 && lane == 0) {
        unsigned bit = 1u << (dst & 31);
        if (!(m1[dst >> 5] & bit)) {
            unsigned old = atomicOr(&g_mask[MASKW + (dst >> 5)], bit);
            if (!(old & bit)) s_list1[atomicAdd(&s_n1, 1)] = dst;
        }
    }
    __syncthreads();
    if (threadIdx.x == 0 && s_n0 > 0) s_b0 = atomicAdd(&g_count[0], s_n0);
    if (threadIdx.x == 1 && s_n1 > 0) s_b1 = atomicAdd(&g_count[1], s_n1);
    __syncthreads();
    if ((int)threadIdx.x < s_n0)
        g_list[s_b0 + threadIdx.x] = s_list0[threadIdx.x];
    int t1 = (int)threadIdx.x - 32;
    if (t1 >= 0 && t1 < s_n1) g_list[NN + s_b1 + t1] = s_list1[t1];
}

// ---------------------------------------------------------------------------
// fused linear (R3 shape + f32x2): 64 list rows, 256 threads, 4x4 tile.
// Dense fast path: identity row order (coalesced), no list reads.
// ---------------------------------------------------------------------------
__global__ void linear_kernel(const float* __restrict__ lin_w,
                              const float* __restrict__ lin_b,
                              const float* __restrict__ ln_g,
                              const float* __restrict__ ln_b, int l) {
    extern __shared__ float smem[];
    float* W_s = smem;               // [128][64] = 32KB
    float* cat_s = smem + 128 * 64;  // [k][node] transposed = 32KB
    __shared__ int idx_s[64];
    int b = blockIdx.y;
    int base = blockIdx.x * 64;
    int t = threadIdx.x;  // 256
    int cnt = g_count[b];
    if (base >= cnt) return;
    bool seq = (cnt == NN);

    if (!seq && t < 64)
        idx_s[t] = (base + t < cnt) ? g_list[b * NN + base + t] : -1;

    const float4* Wg = (const float4*)(lin_w + l * 128 * 64);
    float4* Ws4 = (float4*)W_s;
#pragma unroll
    for (int i = 0; i < 8; i++) Ws4[t + i * 256] = Wg[t + i * 256];
    __syncthreads();

    int nl = t & 63;
    int c0 = t >> 6;  // 0..3
    int idx = seq ? (base + nl) : idx_s[nl];
    const float* xb = g_x + (b * NN + idx) * DD;
    const float* ab = g_agg + (b * NN + idx) * DD;
#pragma unroll
    for (int i = 0; i < 4; i++) {
        int cc = c0 + i * 4;  // float4 col 0..15
        float4 v = make_float4(0.f, 0.f, 0.f, 0.f);
        float4 a = make_float4(0.f, 0.f, 0.f, 0.f);
        if (idx >= 0) {
            v = *(const float4*)&xb[cc * 4];
            a = *(const float4*)&ab[cc * 4];
        }
        cat_s[(cc * 4 + 0) * 64 + nl] = v.x;
        cat_s[(cc * 4 + 1) * 64 + nl] = v.y;
        cat_s[(cc * 4 + 2) * 64 + nl] = v.z;
        cat_s[(cc * 4 + 3) * 64 + nl] = v.w;
        cat_s[(64 + cc * 4 + 0) * 64 + nl] = a.x;
        cat_s[(64 + cc * 4 + 1) * 64 + nl] = a.y;
        cat_s[(64 + cc * 4 + 2) * 64 + nl] = a.z;
        cat_s[(64 + cc * 4 + 3) * 64 + nl] = a.w;
    }
    __syncthreads();

    int tn = t >> 4;  // node group (4 nodes)
    int td = t & 15;  // dim group  (4 dims)
    float4 bias4 = *(const float4*)&lin_b[l * 64 + td * 4];
    unsigned long long accp[4][2];
    {
        unsigned long long b01, b23;
        PACK2(b01, bias4.x, bias4.y);
        PACK2(b23, bias4.z, bias4.w);
#pragma unroll
        for (int i = 0; i < 4; i++) {
            accp[i][0] = b01;
            accp[i][1] = b23;
        }
    }

#pragma unroll 4
    for (int k = 0; k < 128; ++k) {
        const float4 a4 = *(const float4*)(cat_s + k * 64 + tn * 4);
        const ulonglong2 w2 = *(const ulonglong2*)(W_s + k * 64 + td * 4);
        float aa[4] = {a4.x, a4.y, a4.z, a4.w};
#pragma unroll
        for (int i = 0; i < 4; i++) {
            unsigned long long av;
            DUP2(av, aa[i]);
            FMA2(accp[i][0], av, w2.x);
            FMA2(accp[i][1], av, w2.y);
        }
    }

    float acc[4][4];
#pragma unroll
    for (int i = 0; i < 4; i++) {
        UNPACK2(acc[i][0], acc[i][1], accp[i][0]);
        UNPACK2(acc[i][2], acc[i][3], accp[i][1]);
    }

    float4 g4 = *(const float4*)&ln_g[l * 64 + td * 4];
    float4 bb4 = *(const float4*)&ln_b[l * 64 + td * 4];
    float lng[4] = {g4.x, g4.y, g4.z, g4.w};
    float lnb[4] = {bb4.x, bb4.y, bb4.z, bb4.w};
#pragma unroll
    for (int i = 0; i < 4; i++) {
        float s = acc[i][0] + acc[i][1] + acc[i][2] + acc[i][3];
        float s2 = acc[i][0] * acc[i][0] + acc[i][1] * acc[i][1] +
                   acc[i][2] * acc[i][2] + acc[i][3] * acc[i][3];
#pragma unroll
        for (int m = 1; m < 16; m <<= 1) {
            s += __shfl_xor_sync(0xffffffffu, s, m);
            s2 += __shfl_xor_sync(0xffffffffu, s2, m);
        }
        float mu = s * (1.f / 64.f);
        float var = s2 * (1.f / 64.f) - mu * mu;
        float inv = rsqrtf(var + 1e-5f);
        int row = seq ? (base + tn * 4 + i) : idx_s[tn * 4 + i];
        if (row >= 0) {
            float* xr = g_x + (b * NN + row) * DD + td * 4;
            float4 xold = *(const float4*)xr;
            float4 o;
            o.x = fmaxf((acc[i][0] - mu) * inv * lng[0] + lnb[0], 0.f) + xold.x;
            o.y = fmaxf((acc[i][1] - mu) * inv * lng[1] + lnb[1], 0.f) + xold.y;
            o.z = fmaxf((acc[i][2] - mu) * inv * lng[2] + lnb[2], 0.f) + xold.z;
            o.w = fmaxf((acc[i][3] - mu) * inv * lng[3] + lnb[3], 0.f) + xold.w;
            *(float4*)xr = o;
        }
    }
}

// ---------------------------------------------------------------------------
// final: out = relu([x ; query] @ mlp_w + mlp_b); query part precomputed.
// ---------------------------------------------------------------------------
__global__ void final_kernel(const float* __restrict__ mlp_w,
                             float* __restrict__ out) {
    extern __shared__ float smem[];
    float* W_s = smem;             // [64][128] = 32KB
    float* x_s = smem + 64 * 128;  // [k][node] = 16KB
    int b = blockIdx.y;
    int n0 = blockIdx.x * 64;
    int t = threadIdx.x;

    const float4* Wg = (const float4*)mlp_w;
    float4* Ws4 = (float4*)W_s;
#pragma unroll
    for (int i = 0; i < 8; i++) Ws4[t + i * 256] = Wg[t + i * 256];

    const float* xb = g_x + (b * NN + n0) * DD;
    int nl = t & 63;
    int c0 = t >> 6;
#pragma unroll
    for (int i = 0; i < 4; i++) {
        int cc = c0 + i * 4;
        float4 v = *(const float4*)&xb[nl * DD + cc * 4];
        x_s[(cc * 4 + 0) * 64 + nl] = v.x;
        x_s[(cc * 4 + 1) * 64 + nl] = v.y;
        x_s[(cc * 4 + 2) * 64 + nl] = v.z;
        x_s[(cc * 4 + 3) * 64 + nl] = v.w;
    }
    __syncthreads();

    int tn = t >> 4;  // 16 node groups (4 nodes each)
    int td = t & 15;  // 16 dim groups (8 dims each)
    unsigned long long accp[4][4];
#pragma unroll
    for (int i = 0; i < 4; i++)
#pragma unroll
        for (int j = 0; j < 4; j++) accp[i][j] = 0ull;

#pragma unroll 4
    for (int k = 0; k < 64; ++k) {
        const float4 a4 = *(const float4*)(x_s + k * 64 + tn * 4);
        const ulonglong2 w01 = *(const ulonglong2*)(W_s + k * 128 + td * 8);
        const ulonglong2 w23 =
            *(const ulonglong2*)(W_s + k * 128 + td * 8 + 4);
        float aa[4] = {a4.x, a4.y, a4.z, a4.w};
#pragma unroll
        for (int i = 0; i < 4; i++) {
            unsigned long long av;
            DUP2(av, aa[i]);
            FMA2(accp[i][0], av, w01.x);
            FMA2(accp[i][1], av, w01.y);
            FMA2(accp[i][2], av, w23.x);
            FMA2(accp[i][3], av, w23.y);
        }
    }

    float qp[8];
    const float4 q0 = *(const float4*)&g_qpart[b * 128 + td * 8];
    const float4 q1 = *(const float4*)&g_qpart[b * 128 + td * 8 + 4];
    qp[0] = q0.x; qp[1] = q0.y; qp[2] = q0.z; qp[3] = q0.w;
    qp[4] = q1.x; qp[5] = q1.y; qp[6] = q1.z; qp[7] = q1.w;

#pragma unroll
    for (int i = 0; i < 4; i++) {
        float acc[8];
        UNPACK2(acc[0], acc[1], accp[i][0]);
        UNPACK2(acc[2], acc[3], accp[i][1]);
        UNPACK2(acc[4], acc[5], accp[i][2]);
        UNPACK2(acc[6], acc[7], accp[i][3]);
        int n = n0 + tn * 4 + i;
        float* op = out + ((long)(b * NN + n)) * 128 + td * 8;
        float4 o0, o1;
        o0.x = fmaxf(acc[0] + qp[0], 0.f);
        o0.y = fmaxf(acc[1] + qp[1], 0.f);
        o0.z = fmaxf(acc[2] + qp[2], 0.f);
        o0.w = fmaxf(acc[3] + qp[3], 0.f);
        o1.x = fmaxf(acc[4] + qp[4], 0.f);
        o1.y = fmaxf(acc[5] + qp[5], 0.f);
        o1.z = fmaxf(acc[6] + qp[6], 0.f);
        o1.w = fmaxf(acc[7] + qp[7], 0.f);
        *(float4*)op = o0;
        *(float4*)(op + 4) = o1;
    }
}

// ---------------------------------------------------------------------------
extern "C" void kernel_launch(void* const* d_in, const int* in_sizes, int n_in,
                              void* d_out, int out_size) {
    const float* rel_reps = (const float*)d_in[0];
    const int* h_index = (const int*)d_in[1];
    const int* r_index = (const int*)d_in[2];
    const int* edge_index = (const int*)d_in[3];
    const int* edge_type = (const int*)d_in[4];
    const float* pw1 = (const float*)d_in[5];
    const float* pb1 = (const float*)d_in[6];
    const float* pw2 = (const float*)d_in[7];
    const float* pb2 = (const float*)d_in[8];
    const float* lin_w = (const float*)d_in[9];
    const float* lin_b = (const float*)d_in[10];
    const float* ln_g = (const float*)d_in[11];
    const float* ln_b = (const float*)d_in[12];
    const float* mlp_w = (const float*)d_in[13];
    const float* mlp_b = (const float*)d_in[14];
    float* out = (float*)d_out;

    cudaFuncSetAttribute(linear_kernel,
                         cudaFuncAttributeMaxDynamicSharedMemorySize, 65536);
    cudaFuncSetAttribute(final_kernel,
                         cudaFuncAttributeMaxDynamicSharedMemorySize, 49152);

    prep_kernel<<<1, 256>>>(rel_reps, r_index, h_index, mlp_w, mlp_b, lin_b,
                            ln_g, ln_b);
    setup_kernel<<<INITB + RELB + HISTB, 256>>>(h_index, rel_reps, pw1, pb1,
                                                pw2, pb2, edge_index);
    csr_scan1<<<SCANB, 256>>>();
    csr_scan3<<<SCANB, 256>>>();
    csr_scatter<<<(EE + 255) / 256, 256>>>(edge_index, edge_type);
    for (int l = 0; l < LLAYERS; l++) {
        gather_kernel<<<NN / 8, 256>>>(h_index, l);
        linear_kernel<<<dim3((NN + 63) / 64, BB), 256, 65536>>>(lin_w, lin_b,
                                                                ln_g, ln_b, l);
    }
    final_kernel<<<dim3(NN / 64, BB), 256, 49152>>>(mlp_w, out);
}

// round 17
// speedup vs baseline: 1.1403x; 1.1403x over previous
#include <cuda_runtime.h>

#define BB 2
#define NN 40000
#define EE 400000
#define RR 64
#define DD 64
#define LLAYERS 6
#define MASKW 1250   // (NN+31)/32
#define SCANB 157    // (NN+255)/256

#define FMA2(acc, a, b) \
    asm("fma.rn.f32x2 %0, %1, %2, %0;" : "+l"(acc) : "l"(a), "l"(b))
#define PACK2(dst, lo, hi) \
    asm("mov.b64 %0, {%1,%2};" : "=l"(dst) : "r"(__float_as_uint(lo)), "r"(__float_as_uint(hi)))
#define DUP2(dst, v) \
    asm("mov.b64 %0, {%1,%1};" : "=l"(dst) : "r"(__float_as_uint(v)))
#define UNPACK2(lo, hi, src)                          \
    do {                                              \
        unsigned _ulo, _uhi;                          \
        asm("mov.b64 {%0,%1}, %2;"                    \
            : "=r"(_ulo), "=r"(_uhi) : "l"(src));     \
        lo = __uint_as_float(_ulo);                   \
        hi = __uint_as_float(_uhi);                   \
    } while (0)

// Scratch (allocation-free rule: __device__ globals)
__device__ __align__(16) float g_x[BB * NN * DD];
__device__ __align__(16) float g_agg[BB * NN * DD];  // gather OVERWRITES listed rows every layer
__device__ __align__(16) float g_rel[LLAYERS * BB * RR * DD];
__device__ __align__(16) float g_query[BB * DD];
__device__ __align__(16) float g_qpart[BB * 2 * DD];
__device__ unsigned g_mask[BB * MASKW];  // bit set <=> node is in g_list
__device__ int g_list[BB * NN];          // persistent, monotone across layers
__device__ int g_count[BB];
__device__ int g_dense;
// CSR by dst (shared by both batches — same graph); {src,ty} materialized
__device__ int g_cnt[NN];  // zero at launch entry/exit (BSS + scan1 restore)
__device__ int g_fill[NN];
__device__ int g_csr_ptr[NN + 1];
__device__ __align__(16) int2 g_csr_st[EE];
__device__ int g_bsum[SCANB + 3];

// ---------------------------------------------------------------------------
// prep: masks, query, dense flag, list seed {h}, qpart
// ---------------------------------------------------------------------------
__global__ void prep_kernel(const float* __restrict__ rel_reps,
                            const int* __restrict__ r_index,
                            const int* __restrict__ h_index,
                            const float* __restrict__ mlp_w,
                            const float* __restrict__ mlp_b,
                            const float* __restrict__ lin_b,
                            const float* __restrict__ ln_g,
                            const float* __restrict__ ln_b) {
    __shared__ float q_s[BB * DD];
    int t = threadIdx.x;  // 256
    for (int i = t; i < BB * MASKW; i += 256) g_mask[i] = 0u;
    if (t < BB * DD) {
        int b = t / DD, d = t % DD;
        float v = rel_reps[(b * RR + r_index[b]) * DD + d];
        g_query[t] = v;
        q_s[t] = v;
    }
    if (t == 0) {
        int dense = 0;
        for (int l = 0; l < LLAYERS; l++) {
            const float* lb = lin_b + l * DD;
            float mu = 0.f;
            for (int d = 0; d < DD; d++) mu += lb[d];
            mu *= (1.f / DD);
            float var = 0.f;
            for (int d = 0; d < DD; d++) {
                float dv = lb[d] - mu;
                var += dv * dv;
            }
            var *= (1.f / DD);
            float inv = rsqrtf(var + 1e-5f);
            for (int d = 0; d < DD; d++) {
                float o = (lb[d] - mu) * inv * ln_g[l * DD + d] + ln_b[l * DD + d];
                if (o > 0.f) dense = 1;
            }
        }
        g_dense = dense;
    }
    __syncthreads();
    if (t < BB) {
        int h = h_index[t];
        g_mask[t * MASKW + (h >> 5)] = 1u << (h & 31);
        g_count[t] = g_dense ? NN : 1;
        g_list[t * NN] = h;
    }
    int b = t / 128, e = t % 128;
    float acc = mlp_b[e];
#pragma unroll
    for (int k = 0; k < DD; k++)
        acc = fmaf(q_s[b * DD + k], mlp_w[(DD + k) * 128 + e], acc);
    g_qpart[b * 128 + e] = acc;
}

// ---------------------------------------------------------------------------
// CSR build. g_cnt is zero at entry (BSS first time; scan1 restores zero).
// ---------------------------------------------------------------------------
__global__ void csr_hist(const int* __restrict__ edge_index) {
    int e = blockIdx.x * 256 + threadIdx.x;
    if (e < EE) atomicAdd(&g_cnt[__ldg(&edge_index[EE + e])], 1);
}
__global__ void csr_scan1() {
    __shared__ int sh[256];
    int t = threadIdx.x;
    int i = blockIdx.x * 256 + t;
    int v = 0;
    if (i < NN) {
        v = g_cnt[i];
        g_cnt[i] = 0;  // restore zero for next launch/replay
    }
    sh[t] = v;
    __syncthreads();
#pragma unroll
    for (int off = 1; off < 256; off <<= 1) {
        int u = (t >= off) ? sh[t - off] : 0;
        __syncthreads();
        sh[t] += u;
        __syncthreads();
    }
    if (t == 255) g_bsum[blockIdx.x] = sh[255];
    if (i < NN) g_csr_ptr[i] = sh[t] - v;
}
__global__ void csr_scan3() {
    __shared__ int sh[256];
    int t = threadIdx.x;
    int v = (t < SCANB) ? g_bsum[t] : 0;
    sh[t] = v;
    __syncthreads();
#pragma unroll
    for (int off = 1; off < 256; off <<= 1) {
        int u = (t >= off) ? sh[t - off] : 0;
        __syncthreads();
        sh[t] += u;
        __syncthreads();
    }
    __shared__ int s_off;
    if (t == 0) s_off = (blockIdx.x == 0) ? 0 : sh[blockIdx.x - 1];
    __syncthreads();
    int i = blockIdx.x * 256 + t;
    if (i < NN) {
        int p = g_csr_ptr[i] + s_off;
        g_csr_ptr[i] = p;
        g_fill[i] = p;
    }
    if (i == 0) g_csr_ptr[NN] = EE;
}
__global__ void csr_scatter(const int* __restrict__ edge_index,
                            const int* __restrict__ edge_type) {
    int e = blockIdx.x * 256 + threadIdx.x;
    if (e >= EE) return;
    int src = __ldg(&edge_index[e]);
    int dst = __ldg(&edge_index[EE + e]);
    int ty = __ldg(&edge_type[e]);
    int pos = atomicAdd(&g_fill[dst], 1);
    g_csr_st[pos] = make_int2(src, ty);
}

// ---------------------------------------------------------------------------
// init x: zeros everywhere, query at h_index[b].
// Dense fallback: identity list + all-ones mask.
// ---------------------------------------------------------------------------
__global__ void init_x(const int* __restrict__ h_index) {
    int gid = blockIdx.x * 256 + threadIdx.x;
    const int per_b = NN * DD / 4;
    if (gid >= BB * per_b) return;
    if (g_dense) {
        if (gid < BB * NN) g_list[gid] = gid % NN;
        if (gid < BB * MASKW) g_mask[gid] = 0xffffffffu;
    }
    int b = gid / per_b;
    int r = gid - b * per_b;
    int n = r >> 4;
    int d4 = r & 15;
    float4 v = make_float4(0.f, 0.f, 0.f, 0.f);
    if (n == __ldg(&h_index[b]))
        v = *(const float4*)&g_query[b * DD + d4 * 4];
    ((float4*)g_x)[gid] = v;
}

// ---------------------------------------------------------------------------
// ALL layers' relation projections in one kernel (depend only on inputs).
// ---------------------------------------------------------------------------
__global__ void relproj_all(const float* __restrict__ rel_reps,
                            const float* __restrict__ pw1,
                            const float* __restrict__ pb1,
                            const float* __restrict__ pw2,
                            const float* __restrict__ pb2) {
    int blk = blockIdx.x;  // l*(BB*RR) + br
    int l = blk / (BB * RR);
    int br = blk - l * (BB * RR);
    int e = threadIdx.x;  // 64
    __shared__ float in_s[DD];
    __shared__ float hid_s[DD];
    in_s[e] = rel_reps[br * DD + e];
    __syncthreads();
    const float* W1 = pw1 + l * DD * DD;
    float acc = pb1[l * DD + e];
#pragma unroll 16
    for (int k = 0; k < DD; k++) acc = fmaf(in_s[k], W1[k * DD + e], acc);
    hid_s[e] = fmaxf(acc, 0.f);
    __syncthreads();
    const float* W2 = pw2 + l * DD * DD;
    float acc2 = pb2[l * DD + e];
#pragma unroll 16
    for (int k = 0; k < DD; k++) acc2 = fmaf(hid_s[k], W2[k * DD + e], acc2);
    g_rel[blk * DD + e] = acc2;
}

// ---------------------------------------------------------------------------
// gather message: warp handles 4 CONSECUTIVE dsts (grid 1250 = 1 wave, and
// each warp's csr_st reads form one contiguous range). BOTH batches per pass;
// coalesced int2 metadata; union ballot drives per-batch f32x2 accumulation.
// Rows OVERWRITTEN. New dsts appended per block (exactly-once via atomicOr).
// ---------------------------------------------------------------------------
__global__ void __launch_bounds__(256)
gather_kernel(const int* __restrict__ h_index, int l) {
    const unsigned FULL = 0xffffffffu;
    __shared__ int s_list0[32], s_list1[32];
    __shared__ int s_n0, s_n1, s_b0, s_b1;
    if (threadIdx.x == 0) { s_n0 = 0; s_n1 = 0; }
    int warp = threadIdx.x >> 5;
    int lane = threadIdx.x & 31;
    int dst0 = blockIdx.x * 32 + warp * 4;  // NN % 32 == 0
    const unsigned* m0 = g_mask;
    const unsigned* m1 = g_mask + MASKW;
    const float* rel0 = g_rel + (l * BB + 0) * RR * DD;
    const float* rel1 = g_rel + (l * BB + 1) * RR * DD;
    int h0 = __ldg(&h_index[0]);
    int h1 = __ldg(&h_index[1]);
    __syncthreads();

#pragma unroll 1
    for (int j = 0; j < 4; j++) {
        int dst = dst0 + j;
        int beg = __ldg(&g_csr_ptr[dst]);
        int end = __ldg(&g_csr_ptr[dst + 1]);
        unsigned long long acc0 = 0ull, acc1 = 0ull;
        bool any0 = false, any1 = false;
        for (int base = beg; base < end; base += 32) {
            int i = base + lane;
            int src = 0, ty = 0;
            bool a0 = false, a1 = false;
            if (i < end) {
                int2 st = __ldg(&g_csr_st[i]);  // coalesced 8B load
                src = st.x;
                ty = st.y;
                a0 = (m0[src >> 5] >> (src & 31)) & 1u;
                a1 = (m1[src >> 5] >> (src & 31)) & 1u;
            }
            unsigned ball0 = __ballot_sync(FULL, a0);
            unsigned ball1 = __ballot_sync(FULL, a1);
            any0 |= (ball0 != 0);
            any1 |= (ball1 != 0);
            unsigned ball = ball0 | ball1;
            while (ball) {
                int lx = __ffs(ball) - 1;
                ball &= ball - 1;
                int s = __shfl_sync(FULL, src, lx);
                int tt = __shfl_sync(FULL, ty, lx);
                if ((ball0 >> lx) & 1u) {
                    unsigned long long xv =
                        *(const unsigned long long*)&g_x[s * DD + lane * 2];
                    unsigned long long rv =
                        *(const unsigned long long*)&rel0[tt * DD + lane * 2];
                    FMA2(acc0, xv, rv);
                }
                if ((ball1 >> lx) & 1u) {
                    unsigned long long xv =
                        *(const unsigned long long*)&g_x[(NN + s) * DD +
                                                         lane * 2];
                    unsigned long long rv =
                        *(const unsigned long long*)&rel1[tt * DD + lane * 2];
                    FMA2(acc1, xv, rv);
                }
            }
        }
        float a0x, a0y, a1x, a1y;
        UNPACK2(a0x, a0y, acc0);
        UNPACK2(a1x, a1y, acc1);
        if (dst == h0) {
            float2 q = *(const float2*)&g_query[lane * 2];
            a0x += q.x; a0y += q.y;
            any0 = true;
        }
        if (dst == h1) {
            float2 q = *(const float2*)&g_query[DD + lane * 2];
            a1x += q.x; a1y += q.y;
            any1 = true;
        }
        if (any0) {
            *(float2*)&g_agg[dst * DD + lane * 2] = make_float2(a0x, a0y);
            if (lane == 0) {
                unsigned bit = 1u << (dst & 31);
                if (!(m0[dst >> 5] & bit)) {
                    unsigned old = atomicOr(&g_mask[dst >> 5], bit);
                    if (!(old & bit)) s_list0[atomicAdd(&s_n0, 1)] = dst;
                }
            }
        }
        if (any1) {
            *(float2*)&g_agg[(NN + dst) * DD + lane * 2] =
                make_float2(a1x, a1y);
            if (lane == 0) {
                unsigned bit = 1u << (dst & 31);
                if (!(m1[dst >> 5] & bit)) {
                    unsigned old = atomicOr(&g_mask[MASKW + (dst >> 5)], bit);
                    if (!(old & bit)) s_list1[atomicAdd(&s_n1, 1)] = dst;
                }
            }
        }
    }
    __syncthreads();
    if (threadIdx.x == 0 && s_n0 > 0) s_b0 = atomicAdd(&g_count[0], s_n0);
    if (threadIdx.x == 1 && s_n1 > 0) s_b1 = atomicAdd(&g_count[1], s_n1);
    __syncthreads();
    if ((int)threadIdx.x < s_n0)
        g_list[s_b0 + threadIdx.x] = s_list0[threadIdx.x];
    int t1 = (int)threadIdx.x - 32;
    if (t1 >= 0 && t1 < s_n1) g_list[NN + s_b1 + t1] = s_list1[t1];
}

// ---------------------------------------------------------------------------
// fused linear (R3 shape + f32x2): 64 list rows, 256 threads, 4x4 tile.
// No agg zeroing — gather overwrites listed rows every layer.
// ---------------------------------------------------------------------------
__global__ void linear_kernel(const float* __restrict__ lin_w,
                              const float* __restrict__ lin_b,
                              const float* __restrict__ ln_g,
                              const float* __restrict__ ln_b, int l) {
    extern __shared__ float smem[];
    float* W_s = smem;               // [128][64] = 32KB
    float* cat_s = smem + 128 * 64;  // [k][node] transposed = 32KB
    __shared__ int idx_s[64];
    int b = blockIdx.y;
    int base = blockIdx.x * 64;
    int t = threadIdx.x;  // 256
    int cnt = g_count[b];
    if (base >= cnt) return;

    if (t < 64) idx_s[t] = (base + t < cnt) ? g_list[b * NN + base + t] : -1;

    const float4* Wg = (const float4*)(lin_w + l * 128 * 64);
    float4* Ws4 = (float4*)W_s;
#pragma unroll
    for (int i = 0; i < 8; i++) Ws4[t + i * 256] = Wg[t + i * 256];
    __syncthreads();

    int nl = t & 63;
    int c0 = t >> 6;  // 0..3
    int idx = idx_s[nl];
    const float* xb = g_x + (b * NN + idx) * DD;
    const float* ab = g_agg + (b * NN + idx) * DD;
#pragma unroll
    for (int i = 0; i < 4; i++) {
        int cc = c0 + i * 4;  // float4 col 0..15
        float4 v = make_float4(0.f, 0.f, 0.f, 0.f);
        float4 a = make_float4(0.f, 0.f, 0.f, 0.f);
        if (idx >= 0) {
            v = *(const float4*)&xb[cc * 4];
            a = *(const float4*)&ab[cc * 4];
        }
        cat_s[(cc * 4 + 0) * 64 + nl] = v.x;
        cat_s[(cc * 4 + 1) * 64 + nl] = v.y;
        cat_s[(cc * 4 + 2) * 64 + nl] = v.z;
        cat_s[(cc * 4 + 3) * 64 + nl] = v.w;
        cat_s[(64 + cc * 4 + 0) * 64 + nl] = a.x;
        cat_s[(64 + cc * 4 + 1) * 64 + nl] = a.y;
        cat_s[(64 + cc * 4 + 2) * 64 + nl] = a.z;
        cat_s[(64 + cc * 4 + 3) * 64 + nl] = a.w;
    }
    __syncthreads();

    int tn = t >> 4;  // node group (4 nodes)
    int td = t & 15;  // dim group  (4 dims)
    float4 bias4 = *(const float4*)&lin_b[l * 64 + td * 4];
    unsigned long long accp[4][2];
    {
        unsigned long long b01, b23;
        PACK2(b01, bias4.x, bias4.y);
        PACK2(b23, bias4.z, bias4.w);
#pragma unroll
        for (int i = 0; i < 4; i++) {
            accp[i][0] = b01;
            accp[i][1] = b23;
        }
    }

#pragma unroll 4
    for (int k = 0; k < 128; ++k) {
        const float4 a4 = *(const float4*)(cat_s + k * 64 + tn * 4);
        const ulonglong2 w2 = *(const ulonglong2*)(W_s + k * 64 + td * 4);
        float aa[4] = {a4.x, a4.y, a4.z, a4.w};
#pragma unroll
        for (int i = 0; i < 4; i++) {
            unsigned long long av;
            DUP2(av, aa[i]);
            FMA2(accp[i][0], av, w2.x);
            FMA2(accp[i][1], av, w2.y);
        }
    }

    float acc[4][4];
#pragma unroll
    for (int i = 0; i < 4; i++) {
        UNPACK2(acc[i][0], acc[i][1], accp[i][0]);
        UNPACK2(acc[i][2], acc[i][3], accp[i][1]);
    }

    float4 g4 = *(const float4*)&ln_g[l * 64 + td * 4];
    float4 bb4 = *(const float4*)&ln_b[l * 64 + td * 4];
    float lng[4] = {g4.x, g4.y, g4.z, g4.w};
    float lnb[4] = {bb4.x, bb4.y, bb4.z, bb4.w};
#pragma unroll
    for (int i = 0; i < 4; i++) {
        float s = acc[i][0] + acc[i][1] + acc[i][2] + acc[i][3];
        float s2 = acc[i][0] * acc[i][0] + acc[i][1] * acc[i][1] +
                   acc[i][2] * acc[i][2] + acc[i][3] * acc[i][3];
#pragma unroll
        for (int m = 1; m < 16; m <<= 1) {
            s += __shfl_xor_sync(0xffffffffu, s, m);
            s2 += __shfl_xor_sync(0xffffffffu, s2, m);
        }
        float mu = s * (1.f / 64.f);
        float var = s2 * (1.f / 64.f) - mu * mu;
        float inv = rsqrtf(var + 1e-5f);
        int row = idx_s[tn * 4 + i];
        if (row >= 0) {
            float* xr = g_x + (b * NN + row) * DD + td * 4;
            float4 xold = *(const float4*)xr;
            float4 o;
            o.x = fmaxf((acc[i][0] - mu) * inv * lng[0] + lnb[0], 0.f) + xold.x;
            o.y = fmaxf((acc[i][1] - mu) * inv * lng[1] + lnb[1], 0.f) + xold.y;
            o.z = fmaxf((acc[i][2] - mu) * inv * lng[2] + lnb[2], 0.f) + xold.z;
            o.w = fmaxf((acc[i][3] - mu) * inv * lng[3] + lnb[3], 0.f) + xold.w;
            *(float4*)xr = o;
        }
    }
}

// ---------------------------------------------------------------------------
// final: out = relu([x ; query] @ mlp_w + mlp_b); query part precomputed.
// ---------------------------------------------------------------------------
__global__ void final_kernel(const float* __restrict__ mlp_w,
                             float* __restrict__ out) {
    extern __shared__ float smem[];
    float* W_s = smem;             // [64][128] = 32KB
    float* x_s = smem + 64 * 128;  // [k][node] = 16KB
    int b = blockIdx.y;
    int n0 = blockIdx.x * 64;
    int t = threadIdx.x;

    const float4* Wg = (const float4*)mlp_w;
    float4* Ws4 = (float4*)W_s;
#pragma unroll
    for (int i = 0; i < 8; i++) Ws4[t + i * 256] = Wg[t + i * 256];

    const float* xb = g_x + (b * NN + n0) * DD;
    int nl = t & 63;
    int c0 = t >> 6;
#pragma unroll
    for (int i = 0; i < 4; i++) {
        int cc = c0 + i * 4;
        float4 v = *(const float4*)&xb[nl * DD + cc * 4];
        x_s[(cc * 4 + 0) * 64 + nl] = v.x;
        x_s[(cc * 4 + 1) * 64 + nl] = v.y;
        x_s[(cc * 4 + 2) * 64 + nl] = v.z;
        x_s[(cc * 4 + 3) * 64 + nl] = v.w;
    }
    __syncthreads();

    int tn = t >> 4;  // 16 node groups (4 nodes each)
    int td = t & 15;  // 16 dim groups (8 dims each)
    unsigned long long accp[4][4];
#pragma unroll
    for (int i = 0; i < 4; i++)
#pragma unroll
        for (int j = 0; j < 4; j++) accp[i][j] = 0ull;

#pragma unroll 4
    for (int k = 0; k < 64; ++k) {
        const float4 a4 = *(const float4*)(x_s + k * 64 + tn * 4);
        const ulonglong2 w01 = *(const ulonglong2*)(W_s + k * 128 + td * 8);
        const ulonglong2 w23 =
            *(const ulonglong2*)(W_s + k * 128 + td * 8 + 4);
        float aa[4] = {a4.x, a4.y, a4.z, a4.w};
#pragma unroll
        for (int i = 0; i < 4; i++) {
            unsigned long long av;
            DUP2(av, aa[i]);
            FMA2(accp[i][0], av, w01.x);
            FMA2(accp[i][1], av, w01.y);
            FMA2(accp[i][2], av, w23.x);
            FMA2(accp[i][3], av, w23.y);
        }
    }

    float qp[8];
    const float4 q0 = *(const float4*)&g_qpart[b * 128 + td * 8];
    const float4 q1 = *(const float4*)&g_qpart[b * 128 + td * 8 + 4];
    qp[0] = q0.x; qp[1] = q0.y; qp[2] = q0.z; qp[3] = q0.w;
    qp[4] = q1.x; qp[5] = q1.y; qp[6] = q1.z; qp[7] = q1.w;

#pragma unroll
    for (int i = 0; i < 4; i++) {
        float acc[8];
        UNPACK2(acc[0], acc[1], accp[i][0]);
        UNPACK2(acc[2], acc[3], accp[i][1]);
        UNPACK2(acc[4], acc[5], accp[i][2]);
        UNPACK2(acc[6], acc[7], accp[i][3]);
        int n = n0 + tn * 4 + i;
        float* op = out + ((long)(b * NN + n)) * 128 + td * 8;
        float4 o0, o1;
        o0.x = fmaxf(acc[0] + qp[0], 0.f);
        o0.y = fmaxf(acc[1] + qp[1], 0.f);
        o0.z = fmaxf(acc[2] + qp[2], 0.f);
        o0.w = fmaxf(acc[3] + qp[3], 0.f);
        o1.x = fmaxf(acc[4] + qp[4], 0.f);
        o1.y = fmaxf(acc[5] + qp[5], 0.f);
        o1.z = fmaxf(acc[6] + qp[6], 0.f);
        o1.w = fmaxf(acc[7] + qp[7], 0.f);
        *(float4*)op = o0;
        *(float4*)(op + 4) = o1;
    }
}

// ---------------------------------------------------------------------------
extern "C" void kernel_launch(void* const* d_in, const int* in_sizes, int n_in,
                              void* d_out, int out_size) {
    const float* rel_reps = (const float*)d_in[0];
    const int* h_index = (const int*)d_in[1];
    const int* r_index = (const int*)d_in[2];
    const int* edge_index = (const int*)d_in[3];
    const int* edge_type = (const int*)d_in[4];
    const float* pw1 = (const float*)d_in[5];
    const float* pb1 = (const float*)d_in[6];
    const float* pw2 = (const float*)d_in[7];
    const float* pb2 = (const float*)d_in[8];
    const float* lin_w = (const float*)d_in[9];
    const float* lin_b = (const float*)d_in[10];
    const float* ln_g = (const float*)d_in[11];
    const float* ln_b = (const float*)d_in[12];
    const float* mlp_w = (const float*)d_in[13];
    const float* mlp_b = (const float*)d_in[14];
    float* out = (float*)d_out;

    cudaFuncSetAttribute(linear_kernel,
                         cudaFuncAttributeMaxDynamicSharedMemorySize, 65536);
    cudaFuncSetAttribute(final_kernel,
                         cudaFuncAttributeMaxDynamicSharedMemorySize, 49152);

    prep_kernel<<<1, 256>>>(rel_reps, r_index, h_index, mlp_w, mlp_b, lin_b,
                            ln_g, ln_b);
    csr_hist<<<(EE + 255) / 256, 256>>>(edge_index);
    csr_scan1<<<SCANB, 256>>>();
    csr_scan3<<<SCANB, 256>>>();
    csr_scatter<<<(EE + 255) / 256, 256>>>(edge_index, edge_type);
    init_x<<<(BB * NN * DD / 4 + 255) / 256, 256>>>(h_index);
    relproj_all<<<LLAYERS * BB * RR, 64>>>(rel_reps, pw1, pb1, pw2, pb2);
    for (int l = 0; l < LLAYERS; l++) {
        gather_kernel<<<NN / 32, 256>>>(h_index, l);
        linear_kernel<<<dim3((NN + 63) / 64, BB), 256, 65536>>>(lin_w, lin_b,
                                                                ln_g, ln_b, l);
    }
    final_kernel<<<dim3(NN / 64, BB), 256, 49152>>>(mlp_w, out);
}